// round 15
// baseline (speedup 1.0000x reference)
#include <cuda_runtime.h>
#include <cuda_fp16.h>
#include <cstdint>

#define E_DIM 2048
#define T_DIM 2048
#define B_DIM 4
#define D_DIM 1024
#define BT_DIM 8192
#define N_ST 64

typedef unsigned long long u64;

// ---------------- scratch (device globals; no allocation allowed) ----------
static __device__ __align__(1024) float  g_xz [(size_t)BT_DIM * E_DIM];
static __device__ __align__(1024) __half g_szh[(size_t)BT_DIM * E_DIM];
static __device__ __align__(1024) float  g_xc [(size_t)BT_DIM * E_DIM];
static __device__ __align__(1024) float  g_dt [(size_t)BT_DIM * E_DIM];
static __device__ __align__(1024) float  g_Bp [(size_t)BT_DIM * N_ST];
static __device__ __align__(1024) float  g_Cp [(size_t)BT_DIM * N_ST];
// fp16 activations
static __device__ __align__(1024) __half g_xh  [(size_t)BT_DIM * D_DIM];
static __device__ __align__(1024) __half g_xch [(size_t)BT_DIM * E_DIM];
static __device__ __align__(1024) __half g_ywh [(size_t)BT_DIM * E_DIM];
// fp16 hi/lo transposed weights [N,K]
static __device__ __align__(1024) __half g_WinTh [(size_t)4096 * 1024];
static __device__ __align__(1024) __half g_WinTl [(size_t)4096 * 1024];
static __device__ __align__(1024) __half g_WdtTh [(size_t)2048 * 2048];
static __device__ __align__(1024) __half g_WoutTh[(size_t)1024 * 2048];
static __device__ __align__(1024) __half g_WoutTl[(size_t)1024 * 2048];
static __device__ __align__(1024) __half g_WbcH  [(size_t)128 * 2048];
static __device__ __align__(1024) __half g_WbcL  [(size_t)128 * 2048];

__device__ __forceinline__ float silu_f(float v) { return v / (1.f + __expf(-v)); }

// ---------------- PTX helpers ----------------------------------------------
__device__ __forceinline__ uint32_t s2u(const void* p) {
    uint32_t a;
    asm("{ .reg .u64 t; cvta.to.shared.u64 t, %1; cvt.u32.u64 %0, t; }" : "=r"(a) : "l"(p));
    return a;
}
__device__ __forceinline__ uint32_t sw128(uint32_t off) { return off ^ ((off >> 3) & 0x70); }

#define CPA16(dst, src) asm volatile("cp.async.cg.shared.global [%0], [%1], 16;" :: "r"(dst), "l"(src))
#define CPA_COMMIT()    asm volatile("cp.async.commit_group;" ::: "memory")
#define CPA_WAIT2()     asm volatile("cp.async.wait_group 2;" ::: "memory")
#define CPA_WAIT1()     asm volatile("cp.async.wait_group 1;" ::: "memory")
#define CPA_WAIT0()     asm volatile("cp.async.wait_group 0;" ::: "memory")

__device__ __forceinline__ void ldsm4(uint32_t r[4], uint32_t a) {
    asm volatile("ldmatrix.sync.aligned.m8n8.x4.shared.b16 {%0,%1,%2,%3}, [%4];"
        : "=r"(r[0]), "=r"(r[1]), "=r"(r[2]), "=r"(r[3]) : "r"(a));
}
__device__ __forceinline__ void mma_f16(float c[4], const uint32_t a[4],
                                        uint32_t b0, uint32_t b1) {
    asm volatile(
        "mma.sync.aligned.m16n8k16.row.col.f32.f16.f16.f32 "
        "{%0,%1,%2,%3}, {%4,%5,%6,%7}, {%8,%9}, {%0,%1,%2,%3};"
        : "+f"(c[0]), "+f"(c[1]), "+f"(c[2]), "+f"(c[3])
        : "r"(a[0]), "r"(a[1]), "r"(a[2]), "r"(a[3]), "r"(b0), "r"(b1));
}

// packed f32x2
__device__ __forceinline__ u64 pk2(float x, float y) {
    u64 r; asm("mov.b64 %0,{%1,%2};" : "=l"(r) : "f"(x), "f"(y)); return r;
}
__device__ __forceinline__ void unpk2(float& x, float& y, u64 v) {
    asm("mov.b64 {%0,%1}, %2;" : "=f"(x), "=f"(y) : "l"(v));
}
__device__ __forceinline__ u64 f2fma(u64 a, u64 b, u64 c) {
    u64 d; asm("fma.rn.f32x2 %0,%1,%2,%3;" : "=l"(d) : "l"(a), "l"(b), "l"(c)); return d;
}
__device__ __forceinline__ u64 f2mul(u64 a, u64 b) {
    u64 d; asm("mul.rn.f32x2 %0,%1,%2;" : "=l"(d) : "l"(a), "l"(b)); return d;
}
__device__ __forceinline__ void lds2x64(u64& a, u64& b, uint32_t addr) {
    asm volatile("ld.shared.v2.b64 {%0,%1}, [%2];" : "=l"(a), "=l"(b) : "r"(addr));
}

// ---------------- HMMA fp16 GEMM: C[M,N] = A[M,K] * W[K,N] -----------------
// CTA 128x128, BK=64, 8 warps (2m x 4n), warp tile 64x32, 2-stage cp.async.
// MODE 0: plain fp32 store, stride N (split)
// MODE 1: logical N=4096; n0<2048 -> C0 raw fp32 (split); n0>=2048 ->
//         Hz = __half(silu(v)) stride 2048 (no split)
// MODE 4: fused dt + B/C. logical N=2176, grid.x=17.
//         n0<2048: weights Wh (=WdtTh, no split), softplus+clip -> C0 (dtb)
//         n0==2048: weights Wb h/l (=WbcH/WbcL, split); local col<64 -> C1
//         (Bp), else -> C2 (Cp), both stride 64
#define G2_STAGE 49152
#define GEMM_SMEM (2 * G2_STAGE)

template <int MODE, bool SPLIT>
__global__ __launch_bounds__(256, 2)
void gemm_mma(const __half* __restrict__ Ax, const __half* __restrict__ Wh,
              const __half* __restrict__ Wl,
              const __half* __restrict__ Wbh, const __half* __restrict__ Wbl,
              float* __restrict__ C0, float* __restrict__ C1,
              float* __restrict__ C2, __half* __restrict__ Hz,
              const float* __restrict__ bias, int M, int N, int K)
{
    extern __shared__ __align__(1024) char smem[];
    const uint32_t su = s2u(smem);
    const int tid = threadIdx.x;
    const int wid = tid >> 5, lane = tid & 31;
    const int wm = wid & 1, wn = wid >> 1;
    const int n0 = blockIdx.x * 128;
    const int m0 = blockIdx.y * 128;
    const int NT = K >> 6;
    const bool bc = (MODE == 4) && (n0 >= 2048);
    const bool lo_on = (MODE == 4) ? bc
                     : (SPLIT && (MODE != 1 || n0 < 2048));

    const __half* srcA  = Ax + (size_t)m0 * K;
    const __half* srcBh = bc ? Wbh : (Wh + (size_t)n0 * K);
    const __half* srcBl = bc ? Wbl : (Wl ? (Wl + (size_t)n0 * K) : nullptr);

    auto load_stage = [&](int st, int kc) {
        const uint32_t sbase = su + st * G2_STAGE;
        {
            const __half* g0 = srcA + kc * 64;
#pragma unroll
            for (int i = 0; i < 4; i++) {
                int c = tid + i * 256;
                int row = c >> 3, ch = c & 7;
                CPA16(sbase + sw128(row * 128 + ch * 16),
                      g0 + (size_t)row * K + ch * 8);
            }
        }
        {
            const __half* g0 = srcBh + kc * 64;
#pragma unroll
            for (int i = 0; i < 4; i++) {
                int c = tid + i * 256;
                int row = c >> 3, ch = c & 7;
                CPA16(sbase + 16384 + sw128(row * 128 + ch * 16),
                      g0 + (size_t)row * K + ch * 8);
            }
        }
        if (lo_on) {
            const __half* g0 = srcBl + kc * 64;
#pragma unroll
            for (int i = 0; i < 4; i++) {
                int c = tid + i * 256;
                int row = c >> 3, ch = c & 7;
                CPA16(sbase + 32768 + sw128(row * 128 + ch * 16),
                      g0 + (size_t)row * K + ch * 8);
            }
        }
        CPA_COMMIT();
    };

    float acc[4][4][4];
#pragma unroll
    for (int a = 0; a < 4; a++)
#pragma unroll
        for (int b = 0; b < 4; b++)
#pragma unroll
            for (int c = 0; c < 4; c++) acc[a][b][c] = 0.f;

    load_stage(0, 0);

    const int arow = lane & 15;
    const int khalf = lane >> 4;

    uint32_t aAddr[4], bhAddr[2], blAddr[2];
#pragma unroll
    for (int mt = 0; mt < 4; mt++) {
        int r = wm * 64 + mt * 16 + arow;
        aAddr[mt] = su + sw128(r * 128 + khalf * 16);
    }
#pragma unroll
    for (int bt = 0; bt < 2; bt++) {
        int r = wn * 32 + bt * 16 + arow;
        uint32_t sw = sw128(r * 128 + khalf * 16);
        bhAddr[bt] = su + 16384 + sw;
        blAddr[bt] = su + 32768 + sw;
    }

    for (int t = 0; t < NT; ++t) {
        if (t + 1 < NT) { load_stage((t + 1) & 1, t + 1); CPA_WAIT1(); }
        else             CPA_WAIT0();
        __syncthreads();

        const uint32_t soff = (t & 1) * G2_STAGE;
#pragma unroll
        for (int kk = 0; kk < 4; kk++) {
            const uint32_t kx = kk * 32;
            uint32_t bHf[2][4], bLf[2][4];
#pragma unroll
            for (int bt = 0; bt < 2; bt++)
                ldsm4(bHf[bt], (bhAddr[bt] + soff) ^ kx);
            if (lo_on) {
#pragma unroll
                for (int bt = 0; bt < 2; bt++)
                    ldsm4(bLf[bt], (blAddr[bt] + soff) ^ kx);
            }
#pragma unroll
            for (int mt = 0; mt < 4; mt++) {
                uint32_t aF[4];
                ldsm4(aF, (aAddr[mt] + soff) ^ kx);
#pragma unroll
                for (int bt = 0; bt < 2; bt++)
#pragma unroll
                    for (int o = 0; o < 2; o++) {
                        const int j = bt * 2 + o;
                        mma_f16(acc[mt][j], aF, bHf[bt][o], bHf[bt][o + 2]);
                        if (lo_on)
                            mma_f16(acc[mt][j], aF, bLf[bt][o], bLf[bt][o + 2]);
                    }
            }
        }
        __syncthreads();
    }

    // ---------------- epilogue ----------------------------------------------
    const int rbase = m0 + wm * 64 + (lane >> 2);
    const int cbase = n0 + wn * 32 + (lane & 3) * 2;
#pragma unroll
    for (int mt = 0; mt < 4; mt++) {
#pragma unroll
        for (int j = 0; j < 4; j++) {
            const int col = cbase + j * 8;
#pragma unroll
            for (int half = 0; half < 2; half++) {
                const int m = rbase + mt * 16 + half * 8;
                float v0 = acc[mt][j][half * 2];
                float v1 = acc[mt][j][half * 2 + 1];
                if (MODE == 0) {
                    *(float2*)(C0 + (size_t)m * N + col) = make_float2(v0, v1);
                } else if (MODE == 1) {
                    if (n0 < 2048)
                        *(float2*)(C0 + (size_t)m * 2048 + col) = make_float2(v0, v1);
                    else {
                        __half2 hv;
                        hv.x = __float2half(silu_f(v0));
                        hv.y = __float2half(silu_f(v1));
                        *(__half2*)(Hz + (size_t)m * 2048 + (col - 2048)) = hv;
                    }
                } else {    // MODE 4
                    if (!bc) {
                        float u0 = v0 + bias[col], u1 = v1 + bias[col + 1];
                        float s0 = (u0 > 15.f) ? u0 : log1pf(__expf(u0));
                        float s1 = (u1 > 15.f) ? u1 : log1pf(__expf(u1));
                        s0 = fminf(fmaxf(s0, 0.001f), 0.1f);
                        s1 = fminf(fmaxf(s1, 0.001f), 0.1f);
                        *(float2*)(C0 + (size_t)m * 2048 + col) = make_float2(s0, s1);
                    } else {
                        const int lc = col - 2048;
                        if (lc < 64)
                            *(float2*)(C1 + (size_t)m * 64 + lc) = make_float2(v0, v1);
                        else
                            *(float2*)(C2 + (size_t)m * 64 + (lc - 64)) = make_float2(v0, v1);
                    }
                }
            }
        }
    }
}

// ---------------- weight transpose + fp16 hi/lo split -----------------------
__global__ __launch_bounds__(256)
void tsplit_kernel(const float* __restrict__ in, __half* __restrict__ oh,
                   __half* __restrict__ ol, int K, int N)
{
    __shared__ float tile[32][33];
    const int n0 = blockIdx.x * 32, k0 = blockIdx.y * 32;
    const int tx = threadIdx.x & 31, ty = threadIdx.x >> 5;
#pragma unroll
    for (int i = 0; i < 4; i++)
        tile[ty + i * 8][tx] = in[(size_t)(k0 + ty + i * 8) * N + n0 + tx];
    __syncthreads();
#pragma unroll
    for (int i = 0; i < 4; i++) {
        float v = tile[tx][ty + i * 8];
        __half h = __float2half(v);
        size_t o = (size_t)(n0 + ty + i * 8) * K + k0 + tx;
        oh[o] = h;
        if (ol) ol[o] = __float2half(v - __half2float(h));
    }
}

// ---------------- x -> fp16 --------------------------------------------------
__global__ __launch_bounds__(512)
void xcvt_kernel(const float* __restrict__ x, __half* __restrict__ oh)
{
    size_t i = (size_t)blockIdx.x * 512 + threadIdx.x;
    oh[i] = __float2half(x[i]);
}

// ---------------- conv along e, weights indexed by t, + silu ----------------
__global__ __launch_bounds__(256)
void conv_silu_kernel(const float* __restrict__ xz, const float* __restrict__ Wc,
                      float* __restrict__ xc, __half* __restrict__ xch)
{
    __shared__ float s[E_DIM + 4];
    const int row = blockIdx.x;
    const int t = row & (T_DIM - 1);
    const int tid = threadIdx.x;
    const float* src = xz + (size_t)row * E_DIM;
#pragma unroll
    for (int j = 0; j < E_DIM / 256; ++j)
        s[tid + j * 256 + 1] = src[tid + j * 256];
    if (tid == 0) s[0] = 0.f;
    if (tid < 3) s[E_DIM + 1 + tid] = 0.f;
    __syncthreads();
    const float w0 = Wc[t], w1 = Wc[E_DIM + t], w2 = Wc[2 * E_DIM + t], w3 = Wc[3 * E_DIM + t];
    const size_t base = (size_t)row * E_DIM;
#pragma unroll
    for (int j = 0; j < E_DIM / 256; ++j) {
        int e = tid + j * 256;
        float v = w0 * s[e] + w1 * s[e + 1] + w2 * s[e + 2] + w3 * s[e + 3];
        float sv = silu_f(v);
        xc[base + e] = sv;
        xch[base + e] = __float2half(sv);
    }
}

// ---------------- selective scan v3 (sz now fp16) ---------------------------
#define SCAN_CHUNK 32
#define SCAN_NCH   (T_DIM / SCAN_CHUNK)
#define SCAN_SMEM  (4 * 2 * SCAN_CHUNK * N_ST * 4)   // 65536

__global__ __launch_bounds__(512)
void scan_kernel(const float* __restrict__ xc, const float* __restrict__ dt,
                 const float* __restrict__ Bp, const float* __restrict__ Cp,
                 const __half* __restrict__ szh, const float* __restrict__ A_log,
                 __half* __restrict__ yw)
{
    extern __shared__ __align__(1024) char ssm[];
    const uint32_t sbase = s2u(ssm);
    const int tid  = threadIdx.x;
    const int warp = tid >> 5, lane = tid & 31;
    const int sub  = lane & 7;
    const int e0 = (blockIdx.x & 31) * 64;
    const int b  = blockIdx.x >> 5;
    const int e  = e0 + warp * 4 + (lane >> 3);
    const size_t base = ((size_t)b * T_DIM) * E_DIM + e;
    const float* BpB = Bp + (size_t)b * T_DIM * N_ST;
    const float* CpB = Cp + (size_t)b * T_DIM * N_ST;

    u64 A2[4];
#pragma unroll
    for (int p = 0; p < 4; p++)
        A2[p] = pk2(-__expf(A_log[sub * 8 + 2 * p]),
                    -__expf(A_log[sub * 8 + 2 * p + 1]));
    const u64 K24 = pk2(1.f / 24.f, 1.f / 24.f);
    const u64 K6  = pk2(1.f / 6.f, 1.f / 6.f);
    const u64 K05 = pk2(0.5f, 0.5f);
    const u64 K1  = pk2(1.f, 1.f);

    auto issue_chunk = [&](int c) {
        if (c < SCAN_NCH) {
            const uint32_t bufo = sbase + (c & 3) * 16384;
            const float* gB = BpB + (size_t)c * SCAN_CHUNK * N_ST;
            const float* gC = CpB + (size_t)c * SCAN_CHUNK * N_ST;
            CPA16(bufo + tid * 16,        gB + tid * 4);
            CPA16(bufo + 8192 + tid * 16, gC + tid * 4);
        }
        CPA_COMMIT();
    };

    issue_chunk(0); issue_chunk(1); issue_chunk(2);

    float xbuf[4], dbuf[4], sbuf[4];
#pragma unroll
    for (int r = 0; r < 4; r++) {
        const size_t off = base + (size_t)(r * 8 + sub) * E_DIM;
        xbuf[r] = xc[off]; dbuf[r] = dt[off]; sbuf[r] = __half2float(szh[off]);
    }

    u64 h[4] = {0, 0, 0, 0};
    float yreg[4];

    for (int c = 0; c < SCAN_NCH; ++c) {
        CPA_WAIT2();
        __syncthreads();
        issue_chunk(c + 3);

        float xn[4], dn[4], sn[4];
        if (c + 1 < SCAN_NCH) {
#pragma unroll
            for (int r = 0; r < 4; r++) {
                const size_t off = base + (size_t)((c + 1) * SCAN_CHUNK + r * 8 + sub) * E_DIM;
                xn[r] = xc[off]; dn[r] = dt[off]; sn[r] = __half2float(szh[off]);
            }
        } else {
#pragma unroll
            for (int r = 0; r < 4; r++) { xn[r] = 0.f; dn[r] = 0.f; sn[r] = 0.f; }
        }

        const uint32_t bufo = sbase + (c & 3) * 16384 + sub * 32;
#pragma unroll
        for (int r = 0; r < 4; r++) {
#pragma unroll
            for (int ti = 0; ti < 8; ti++) {
                const int tt = r * 8 + ti;
                const float xv  = __shfl_sync(0xFFFFFFFFu, xbuf[r], ti, 8);
                const float dtv = __shfl_sync(0xFFFFFFFFu, dbuf[r], ti, 8);
                const float szv = __shfl_sync(0xFFFFFFFFu, sbuf[r], ti, 8);
                u64 Bv0, Bv1, Bv2, Bv3, Cv0, Cv1, Cv2, Cv3;
                lds2x64(Bv0, Bv1, bufo + tt * 256);
                lds2x64(Bv2, Bv3, bufo + tt * 256 + 16);
                lds2x64(Cv0, Cv1, bufo + 8192 + tt * 256);
                lds2x64(Cv2, Cv3, bufo + 8192 + tt * 256 + 16);

                const u64 dt2  = pk2(dtv, dtv);
                const float dtx = dtv * xv;
                const u64 dtx2 = pk2(dtx, dtx);

                u64 yp;
                {
                    u64 u0 = f2mul(dt2, A2[0]);
                    u64 r0 = f2fma(u0, K24, K6);
                    r0 = f2fma(u0, r0, K05); r0 = f2fma(u0, r0, K1); r0 = f2fma(u0, r0, K1);
                    h[0] = f2fma(r0, h[0], f2mul(dtx2, Bv0));
                    yp = f2mul(h[0], Cv0);
                }
                {
                    u64 u1 = f2mul(dt2, A2[1]);
                    u64 r1 = f2fma(u1, K24, K6);
                    r1 = f2fma(u1, r1, K05); r1 = f2fma(u1, r1, K1); r1 = f2fma(u1, r1, K1);
                    h[1] = f2fma(r1, h[1], f2mul(dtx2, Bv1));
                    yp = f2fma(h[1], Cv1, yp);
                }
                {
                    u64 u2 = f2mul(dt2, A2[2]);
                    u64 r2 = f2fma(u2, K24, K6);
                    r2 = f2fma(u2, r2, K05); r2 = f2fma(u2, r2, K1); r2 = f2fma(u2, r2, K1);
                    h[2] = f2fma(r2, h[2], f2mul(dtx2, Bv2));
                    yp = f2fma(h[2], Cv2, yp);
                }
                {
                    u64 u3 = f2mul(dt2, A2[3]);
                    u64 r3 = f2fma(u3, K24, K6);
                    r3 = f2fma(u3, r3, K05); r3 = f2fma(u3, r3, K1); r3 = f2fma(u3, r3, K1);
                    h[3] = f2fma(r3, h[3], f2mul(dtx2, Bv3));
                    yp = f2fma(h[3], Cv3, yp);
                }
                float y0, y1;
                unpk2(y0, y1, yp);
                float y = y0 + y1;
                y += __shfl_xor_sync(0xFFFFFFFFu, y, 4);
                y += __shfl_xor_sync(0xFFFFFFFFu, y, 2);
                y += __shfl_xor_sync(0xFFFFFFFFu, y, 1);
                if (sub == ti) yreg[r] = y * szv;
            }
        }
#pragma unroll
        for (int r = 0; r < 4; r++) {
            xbuf[r] = xn[r]; dbuf[r] = dn[r]; sbuf[r] = sn[r];
            yw[((size_t)b * T_DIM + c * SCAN_CHUNK + r * 8 + sub) * E_DIM + e] =
                __float2half(yreg[r]);
        }
    }
}

// ---------------------------------------------------------------------------
extern "C" void kernel_launch(void* const* d_in, const int* in_sizes, int n_in,
                              void* d_out, int out_size)
{
    (void)in_sizes; (void)n_in; (void)out_size;
    const float* x      = (const float*)d_in[0];
    const float* W_in   = (const float*)d_in[1];
    const float* W_conv = (const float*)d_in[2];
    const float* W_dt   = (const float*)d_in[3];
    const float* b_dt   = (const float*)d_in[4];
    const float* W_B    = (const float*)d_in[5];
    const float* W_C    = (const float*)d_in[6];
    const float* A_log  = (const float*)d_in[7];
    const float* W_out  = (const float*)d_in[8];
    float* out = (float*)d_out;

    float *xz, *xc, *dtb, *Bpp, *Cpp;
    __half *szh, *xh, *xch, *ywh;
    __half *WinTh, *WinTl, *WdtTh, *WoutTh, *WoutTl, *WbcH, *WbcL;
    cudaGetSymbolAddress((void**)&xz,  g_xz);
    cudaGetSymbolAddress((void**)&szh, g_szh);
    cudaGetSymbolAddress((void**)&xc,  g_xc);
    cudaGetSymbolAddress((void**)&dtb, g_dt);
    cudaGetSymbolAddress((void**)&Bpp, g_Bp);
    cudaGetSymbolAddress((void**)&Cpp, g_Cp);
    cudaGetSymbolAddress((void**)&xh,  g_xh);
    cudaGetSymbolAddress((void**)&xch, g_xch);
    cudaGetSymbolAddress((void**)&ywh, g_ywh);
    cudaGetSymbolAddress((void**)&WinTh,  g_WinTh);
    cudaGetSymbolAddress((void**)&WinTl,  g_WinTl);
    cudaGetSymbolAddress((void**)&WdtTh,  g_WdtTh);
    cudaGetSymbolAddress((void**)&WoutTh, g_WoutTh);
    cudaGetSymbolAddress((void**)&WoutTl, g_WoutTl);
    cudaGetSymbolAddress((void**)&WbcH,   g_WbcH);
    cudaGetSymbolAddress((void**)&WbcL,   g_WbcL);

    cudaFuncSetAttribute((const void*)gemm_mma<0, true>,  cudaFuncAttributeMaxDynamicSharedMemorySize, GEMM_SMEM);
    cudaFuncSetAttribute((const void*)gemm_mma<1, true>,  cudaFuncAttributeMaxDynamicSharedMemorySize, GEMM_SMEM);
    cudaFuncSetAttribute((const void*)gemm_mma<4, false>, cudaFuncAttributeMaxDynamicSharedMemorySize, GEMM_SMEM);
    cudaFuncSetAttribute((const void*)scan_kernel,        cudaFuncAttributeMaxDynamicSharedMemorySize, SCAN_SMEM);

    // 0) x -> fp16
    xcvt_kernel<<<(BT_DIM * D_DIM) / 512, 512>>>(x, xh);
    // 1) W_in transpose+split
    tsplit_kernel<<<dim3(4096 / 32, 1024 / 32), 256>>>(W_in, WinTh, WinTl, 1024, 4096);
    // 2) W_dt transpose (hi only)
    tsplit_kernel<<<dim3(2048 / 32, 2048 / 32), 256>>>(W_dt, WdtTh, nullptr, 2048, 2048);
    // 3) in-projection  <-- ncu capture target
    gemm_mma<1, true><<<dim3(4096 / 128, BT_DIM / 128), 256, GEMM_SMEM>>>(
        xh, WinTh, WinTl, nullptr, nullptr, xz, nullptr, nullptr, szh, nullptr,
        BT_DIM, 4096, 1024);
    // 4) conv along e + silu (+ fp16 copy)
    conv_silu_kernel<<<BT_DIM, 256>>>(xz, W_conv, xc, xch);
    // 5-6) W_B / W_C splits
    tsplit_kernel<<<dim3(64 / 32, 2048 / 32), 256>>>(W_B, WbcH,             WbcL,             2048, 64);
    tsplit_kernel<<<dim3(64 / 32, 2048 / 32), 256>>>(W_C, WbcH + 64 * 2048, WbcL + 64 * 2048, 2048, 64);
    // 7) fused dt + B/C projections (N = 2048 + 128, grid.x = 17)
    gemm_mma<4, false><<<dim3(17, BT_DIM / 128), 256, GEMM_SMEM>>>(
        xch, WdtTh, nullptr, WbcH, WbcL, dtb, Bpp, Cpp, nullptr, b_dt,
        BT_DIM, 2048, 2048);
    // 8) W_out split
    tsplit_kernel<<<dim3(1024 / 32, 2048 / 32), 256>>>(W_out, WoutTh, WoutTl, 2048, 1024);
    // 9) selective scan (fuses y * silu(z), emits fp16)
    scan_kernel<<<B_DIM * (E_DIM / 64), 512, SCAN_SMEM>>>(xc, dtb, Bpp, Cpp, szh, A_log, ywh);
    // 10) out projection (split) -> d_out
    gemm_mma<0, true><<<dim3(D_DIM / 128, BT_DIM / 128), 256, GEMM_SMEM>>>(
        ywh, WoutTh, WoutTl, nullptr, nullptr, out, nullptr, nullptr, nullptr, nullptr,
        BT_DIM, D_DIM, E_DIM);
}

// round 16
// speedup vs baseline: 1.0677x; 1.0677x over previous
#include <cuda_runtime.h>
#include <cuda_fp16.h>
#include <cstdint>

#define E_DIM 2048
#define T_DIM 2048
#define B_DIM 4
#define D_DIM 1024
#define BT_DIM 8192
#define N_ST 64

typedef unsigned long long u64;

// ---------------- scratch (device globals; no allocation allowed) ----------
static __device__ __align__(1024) float  g_xz [(size_t)BT_DIM * E_DIM];
static __device__ __align__(1024) __half g_szh[(size_t)BT_DIM * E_DIM];
static __device__ __align__(1024) float  g_xc [(size_t)BT_DIM * E_DIM];
static __device__ __align__(1024) float  g_dt [(size_t)BT_DIM * E_DIM];
static __device__ __align__(1024) float  g_Bp [(size_t)BT_DIM * N_ST];
static __device__ __align__(1024) float  g_Cp [(size_t)BT_DIM * N_ST];
// fp16 activations
static __device__ __align__(1024) __half g_xh  [(size_t)BT_DIM * D_DIM];
static __device__ __align__(1024) __half g_xch [(size_t)BT_DIM * E_DIM];
static __device__ __align__(1024) __half g_ywh [(size_t)BT_DIM * E_DIM];
// fp16 hi/lo transposed weights [N,K]
static __device__ __align__(1024) __half g_WinTh [(size_t)4096 * 1024];
static __device__ __align__(1024) __half g_WinTl [(size_t)4096 * 1024];
static __device__ __align__(1024) __half g_WdtTh [(size_t)2048 * 2048];
static __device__ __align__(1024) __half g_WoutTh[(size_t)1024 * 2048];
static __device__ __align__(1024) __half g_WoutTl[(size_t)1024 * 2048];
static __device__ __align__(1024) __half g_WbcH  [(size_t)128 * 2048];
static __device__ __align__(1024) __half g_WbcL  [(size_t)128 * 2048];

__device__ __forceinline__ float silu_f(float v) { return v / (1.f + __expf(-v)); }

// ---------------- PTX helpers ----------------------------------------------
__device__ __forceinline__ uint32_t s2u(const void* p) {
    uint32_t a;
    asm("{ .reg .u64 t; cvta.to.shared.u64 t, %1; cvt.u32.u64 %0, t; }" : "=r"(a) : "l"(p));
    return a;
}
__device__ __forceinline__ uint32_t sw128(uint32_t off) { return off ^ ((off >> 3) & 0x70); }

#define CPA16(dst, src) asm volatile("cp.async.cg.shared.global [%0], [%1], 16;" :: "r"(dst), "l"(src))
#define CPA_COMMIT()    asm volatile("cp.async.commit_group;" ::: "memory")
#define CPA_WAIT2()     asm volatile("cp.async.wait_group 2;" ::: "memory")
#define CPA_WAIT1()     asm volatile("cp.async.wait_group 1;" ::: "memory")
#define CPA_WAIT0()     asm volatile("cp.async.wait_group 0;" ::: "memory")

__device__ __forceinline__ void ldsm4(uint32_t r[4], uint32_t a) {
    asm volatile("ldmatrix.sync.aligned.m8n8.x4.shared.b16 {%0,%1,%2,%3}, [%4];"
        : "=r"(r[0]), "=r"(r[1]), "=r"(r[2]), "=r"(r[3]) : "r"(a));
}
__device__ __forceinline__ void mma_f16(float c[4], const uint32_t a[4],
                                        uint32_t b0, uint32_t b1) {
    asm volatile(
        "mma.sync.aligned.m16n8k16.row.col.f32.f16.f16.f32 "
        "{%0,%1,%2,%3}, {%4,%5,%6,%7}, {%8,%9}, {%0,%1,%2,%3};"
        : "+f"(c[0]), "+f"(c[1]), "+f"(c[2]), "+f"(c[3])
        : "r"(a[0]), "r"(a[1]), "r"(a[2]), "r"(a[3]), "r"(b0), "r"(b1));
}

// packed f32x2
__device__ __forceinline__ u64 pk2(float x, float y) {
    u64 r; asm("mov.b64 %0,{%1,%2};" : "=l"(r) : "f"(x), "f"(y)); return r;
}
__device__ __forceinline__ void unpk2(float& x, float& y, u64 v) {
    asm("mov.b64 {%0,%1}, %2;" : "=f"(x), "=f"(y) : "l"(v));
}
__device__ __forceinline__ u64 f2fma(u64 a, u64 b, u64 c) {
    u64 d; asm("fma.rn.f32x2 %0,%1,%2,%3;" : "=l"(d) : "l"(a), "l"(b), "l"(c)); return d;
}
__device__ __forceinline__ u64 f2mul(u64 a, u64 b) {
    u64 d; asm("mul.rn.f32x2 %0,%1,%2;" : "=l"(d) : "l"(a), "l"(b)); return d;
}
__device__ __forceinline__ void lds2x64(u64& a, u64& b, uint32_t addr) {
    asm volatile("ld.shared.v2.b64 {%0,%1}, [%2];" : "=l"(a), "=l"(b) : "r"(addr));
}

// ---------------- HMMA fp16 GEMM: C[M,N] = A[M,K] * W[K,N] -----------------
// CTA 128x128, BK=64, 8 warps (2m x 4n), warp tile 64x32, 2-stage cp.async.
// MODE 0: plain fp32 store, stride N (split)
// MODE 1: logical N=4096; n0<2048 -> C0 raw fp32 (split); n0>=2048 ->
//         Hz = __half(silu(v)) stride 2048 (no split)
// MODE 2: softplus(v + bias[col]) clipped [1e-3,1e-1], stride N (no split)
// MODE 3: logical N=128 in ONE block col; col<64 -> C0, else C1, stride 64
#define G2_STAGE 49152
#define GEMM_SMEM (2 * G2_STAGE)

template <int MODE, bool SPLIT>
__global__ __launch_bounds__(256, 2)
void gemm_mma(const __half* __restrict__ Ax, const __half* __restrict__ Bh,
              const __half* __restrict__ Bl,
              float* __restrict__ C0, float* __restrict__ C1,
              __half* __restrict__ Hz,
              const float* __restrict__ bias, int M, int N, int K)
{
    extern __shared__ __align__(1024) char smem[];
    const uint32_t su = s2u(smem);
    const int tid = threadIdx.x;
    const int wid = tid >> 5, lane = tid & 31;
    const int wm = wid & 1, wn = wid >> 1;
    const int n0 = blockIdx.x * 128;
    const int m0 = blockIdx.y * 128;
    const int NT = K >> 6;
    const bool lo_on = SPLIT && (MODE != 1 || n0 < 2048);

    const __half* srcA  = Ax + (size_t)m0 * K;
    const __half* srcBh = Bh + (size_t)n0 * K;
    const __half* srcBl = Bl ? (Bl + (size_t)n0 * K) : nullptr;

    auto load_stage = [&](int st, int kc) {
        const uint32_t sbase = su + st * G2_STAGE;
        {
            const __half* g0 = srcA + kc * 64;
#pragma unroll
            for (int i = 0; i < 4; i++) {
                int c = tid + i * 256;
                int row = c >> 3, ch = c & 7;
                CPA16(sbase + sw128(row * 128 + ch * 16),
                      g0 + (size_t)row * K + ch * 8);
            }
        }
        {
            const __half* g0 = srcBh + kc * 64;
#pragma unroll
            for (int i = 0; i < 4; i++) {
                int c = tid + i * 256;
                int row = c >> 3, ch = c & 7;
                CPA16(sbase + 16384 + sw128(row * 128 + ch * 16),
                      g0 + (size_t)row * K + ch * 8);
            }
        }
        if (lo_on) {
            const __half* g0 = srcBl + kc * 64;
#pragma unroll
            for (int i = 0; i < 4; i++) {
                int c = tid + i * 256;
                int row = c >> 3, ch = c & 7;
                CPA16(sbase + 32768 + sw128(row * 128 + ch * 16),
                      g0 + (size_t)row * K + ch * 8);
            }
        }
        CPA_COMMIT();
    };

    float acc[4][4][4];
#pragma unroll
    for (int a = 0; a < 4; a++)
#pragma unroll
        for (int b = 0; b < 4; b++)
#pragma unroll
            for (int c = 0; c < 4; c++) acc[a][b][c] = 0.f;

    load_stage(0, 0);

    const int arow = lane & 15;
    const int khalf = lane >> 4;

    uint32_t aAddr[4], bhAddr[2], blAddr[2];
#pragma unroll
    for (int mt = 0; mt < 4; mt++) {
        int r = wm * 64 + mt * 16 + arow;
        aAddr[mt] = su + sw128(r * 128 + khalf * 16);
    }
#pragma unroll
    for (int bt = 0; bt < 2; bt++) {
        int r = wn * 32 + bt * 16 + arow;
        uint32_t sw = sw128(r * 128 + khalf * 16);
        bhAddr[bt] = su + 16384 + sw;
        blAddr[bt] = su + 32768 + sw;
    }

    for (int t = 0; t < NT; ++t) {
        if (t + 1 < NT) { load_stage((t + 1) & 1, t + 1); CPA_WAIT1(); }
        else             CPA_WAIT0();
        __syncthreads();

        const uint32_t soff = (t & 1) * G2_STAGE;
#pragma unroll
        for (int kk = 0; kk < 4; kk++) {
            const uint32_t kx = kk * 32;
            uint32_t bHf[2][4], bLf[2][4];
#pragma unroll
            for (int bt = 0; bt < 2; bt++)
                ldsm4(bHf[bt], (bhAddr[bt] + soff) ^ kx);
            if (lo_on) {
#pragma unroll
                for (int bt = 0; bt < 2; bt++)
                    ldsm4(bLf[bt], (blAddr[bt] + soff) ^ kx);
            }
#pragma unroll
            for (int mt = 0; mt < 4; mt++) {
                uint32_t aF[4];
                ldsm4(aF, (aAddr[mt] + soff) ^ kx);
#pragma unroll
                for (int bt = 0; bt < 2; bt++)
#pragma unroll
                    for (int o = 0; o < 2; o++) {
                        const int j = bt * 2 + o;
                        mma_f16(acc[mt][j], aF, bHf[bt][o], bHf[bt][o + 2]);
                        if (lo_on)
                            mma_f16(acc[mt][j], aF, bLf[bt][o], bLf[bt][o + 2]);
                    }
            }
        }
        __syncthreads();
    }

    // ---------------- epilogue ----------------------------------------------
    const int rbase = m0 + wm * 64 + (lane >> 2);
    const int cbase = n0 + wn * 32 + (lane & 3) * 2;
#pragma unroll
    for (int mt = 0; mt < 4; mt++) {
#pragma unroll
        for (int j = 0; j < 4; j++) {
            const int col = cbase + j * 8;
#pragma unroll
            for (int half = 0; half < 2; half++) {
                const int m = rbase + mt * 16 + half * 8;
                float v0 = acc[mt][j][half * 2];
                float v1 = acc[mt][j][half * 2 + 1];
                if (MODE == 0) {
                    *(float2*)(C0 + (size_t)m * N + col) = make_float2(v0, v1);
                } else if (MODE == 1) {
                    if (n0 < 2048)
                        *(float2*)(C0 + (size_t)m * 2048 + col) = make_float2(v0, v1);
                    else {
                        __half2 hv;
                        hv.x = __float2half(silu_f(v0));
                        hv.y = __float2half(silu_f(v1));
                        *(__half2*)(Hz + (size_t)m * 2048 + (col - 2048)) = hv;
                    }
                } else if (MODE == 2) {
                    float u0 = v0 + bias[col], u1 = v1 + bias[col + 1];
                    float s0 = (u0 > 15.f) ? u0 : log1pf(__expf(u0));
                    float s1 = (u1 > 15.f) ? u1 : log1pf(__expf(u1));
                    s0 = fminf(fmaxf(s0, 0.001f), 0.1f);
                    s1 = fminf(fmaxf(s1, 0.001f), 0.1f);
                    *(float2*)(C0 + (size_t)m * N + col) = make_float2(s0, s1);
                } else {
                    if (col < 64)
                        *(float2*)(C0 + (size_t)m * 64 + col) = make_float2(v0, v1);
                    else
                        *(float2*)(C1 + (size_t)m * 64 + (col - 64)) = make_float2(v0, v1);
                }
            }
        }
    }
}

// ---------------- weight transpose + fp16 hi/lo split -----------------------
__global__ __launch_bounds__(256)
void tsplit_kernel(const float* __restrict__ in, __half* __restrict__ oh,
                   __half* __restrict__ ol, int K, int N)
{
    __shared__ float tile[32][33];
    const int n0 = blockIdx.x * 32, k0 = blockIdx.y * 32;
    const int tx = threadIdx.x & 31, ty = threadIdx.x >> 5;
#pragma unroll
    for (int i = 0; i < 4; i++)
        tile[ty + i * 8][tx] = in[(size_t)(k0 + ty + i * 8) * N + n0 + tx];
    __syncthreads();
#pragma unroll
    for (int i = 0; i < 4; i++) {
        float v = tile[tx][ty + i * 8];
        __half h = __float2half(v);
        size_t o = (size_t)(n0 + ty + i * 8) * K + k0 + tx;
        oh[o] = h;
        if (ol) ol[o] = __float2half(v - __half2float(h));
    }
}

// ---------------- x -> fp16 --------------------------------------------------
__global__ __launch_bounds__(512)
void xcvt_kernel(const float* __restrict__ x, __half* __restrict__ oh)
{
    size_t i = (size_t)blockIdx.x * 512 + threadIdx.x;
    oh[i] = __float2half(x[i]);
}

// ---------------- conv along e, weights indexed by t, + silu ----------------
__global__ __launch_bounds__(256)
void conv_silu_kernel(const float* __restrict__ xz, const float* __restrict__ Wc,
                      float* __restrict__ xc, __half* __restrict__ xch)
{
    __shared__ float s[E_DIM + 4];
    const int row = blockIdx.x;
    const int t = row & (T_DIM - 1);
    const int tid = threadIdx.x;
    const float* src = xz + (size_t)row * E_DIM;
#pragma unroll
    for (int j = 0; j < E_DIM / 256; ++j)
        s[tid + j * 256 + 1] = src[tid + j * 256];
    if (tid == 0) s[0] = 0.f;
    if (tid < 3) s[E_DIM + 1 + tid] = 0.f;
    __syncthreads();
    const float w0 = Wc[t], w1 = Wc[E_DIM + t], w2 = Wc[2 * E_DIM + t], w3 = Wc[3 * E_DIM + t];
    const size_t base = (size_t)row * E_DIM;
#pragma unroll
    for (int j = 0; j < E_DIM / 256; ++j) {
        int e = tid + j * 256;
        float v = w0 * s[e] + w1 * s[e + 1] + w2 * s[e + 2] + w3 * s[e + 3];
        float sv = silu_f(v);
        xc[base + e] = sv;
        xch[base + e] = __float2half(sv);
    }
}

// ---------------- selective scan v3 (sz fp16) --------------------------------
#define SCAN_CHUNK 32
#define SCAN_NCH   (T_DIM / SCAN_CHUNK)
#define SCAN_SMEM  (4 * 2 * SCAN_CHUNK * N_ST * 4)   // 65536

__global__ __launch_bounds__(512)
void scan_kernel(const float* __restrict__ xc, const float* __restrict__ dt,
                 const float* __restrict__ Bp, const float* __restrict__ Cp,
                 const __half* __restrict__ szh, const float* __restrict__ A_log,
                 __half* __restrict__ yw)
{
    extern __shared__ __align__(1024) char ssm[];
    const uint32_t sbase = s2u(ssm);
    const int tid  = threadIdx.x;
    const int warp = tid >> 5, lane = tid & 31;
    const int sub  = lane & 7;
    const int e0 = (blockIdx.x & 31) * 64;
    const int b  = blockIdx.x >> 5;
    const int e  = e0 + warp * 4 + (lane >> 3);
    const size_t base = ((size_t)b * T_DIM) * E_DIM + e;
    const float* BpB = Bp + (size_t)b * T_DIM * N_ST;
    const float* CpB = Cp + (size_t)b * T_DIM * N_ST;

    u64 A2[4];
#pragma unroll
    for (int p = 0; p < 4; p++)
        A2[p] = pk2(-__expf(A_log[sub * 8 + 2 * p]),
                    -__expf(A_log[sub * 8 + 2 * p + 1]));
    const u64 K24 = pk2(1.f / 24.f, 1.f / 24.f);
    const u64 K6  = pk2(1.f / 6.f, 1.f / 6.f);
    const u64 K05 = pk2(0.5f, 0.5f);
    const u64 K1  = pk2(1.f, 1.f);

    auto issue_chunk = [&](int c) {
        if (c < SCAN_NCH) {
            const uint32_t bufo = sbase + (c & 3) * 16384;
            const float* gB = BpB + (size_t)c * SCAN_CHUNK * N_ST;
            const float* gC = CpB + (size_t)c * SCAN_CHUNK * N_ST;
            CPA16(bufo + tid * 16,        gB + tid * 4);
            CPA16(bufo + 8192 + tid * 16, gC + tid * 4);
        }
        CPA_COMMIT();
    };

    issue_chunk(0); issue_chunk(1); issue_chunk(2);

    float xbuf[4], dbuf[4], sbuf[4];
#pragma unroll
    for (int r = 0; r < 4; r++) {
        const size_t off = base + (size_t)(r * 8 + sub) * E_DIM;
        xbuf[r] = xc[off]; dbuf[r] = dt[off]; sbuf[r] = __half2float(szh[off]);
    }

    u64 h[4] = {0, 0, 0, 0};
    float yreg[4];

    for (int c = 0; c < SCAN_NCH; ++c) {
        CPA_WAIT2();
        __syncthreads();
        issue_chunk(c + 3);

        float xn[4], dn[4], sn[4];
        if (c + 1 < SCAN_NCH) {
#pragma unroll
            for (int r = 0; r < 4; r++) {
                const size_t off = base + (size_t)((c + 1) * SCAN_CHUNK + r * 8 + sub) * E_DIM;
                xn[r] = xc[off]; dn[r] = dt[off]; sn[r] = __half2float(szh[off]);
            }
        } else {
#pragma unroll
            for (int r = 0; r < 4; r++) { xn[r] = 0.f; dn[r] = 0.f; sn[r] = 0.f; }
        }

        const uint32_t bufo = sbase + (c & 3) * 16384 + sub * 32;
#pragma unroll
        for (int r = 0; r < 4; r++) {
#pragma unroll
            for (int ti = 0; ti < 8; ti++) {
                const int tt = r * 8 + ti;
                const float xv  = __shfl_sync(0xFFFFFFFFu, xbuf[r], ti, 8);
                const float dtv = __shfl_sync(0xFFFFFFFFu, dbuf[r], ti, 8);
                const float szv = __shfl_sync(0xFFFFFFFFu, sbuf[r], ti, 8);
                u64 Bv0, Bv1, Bv2, Bv3, Cv0, Cv1, Cv2, Cv3;
                lds2x64(Bv0, Bv1, bufo + tt * 256);
                lds2x64(Bv2, Bv3, bufo + tt * 256 + 16);
                lds2x64(Cv0, Cv1, bufo + 8192 + tt * 256);
                lds2x64(Cv2, Cv3, bufo + 8192 + tt * 256 + 16);

                const u64 dt2  = pk2(dtv, dtv);
                const float dtx = dtv * xv;
                const u64 dtx2 = pk2(dtx, dtx);

                u64 yp;
                {
                    u64 u0 = f2mul(dt2, A2[0]);
                    u64 r0 = f2fma(u0, K24, K6);
                    r0 = f2fma(u0, r0, K05); r0 = f2fma(u0, r0, K1); r0 = f2fma(u0, r0, K1);
                    h[0] = f2fma(r0, h[0], f2mul(dtx2, Bv0));
                    yp = f2mul(h[0], Cv0);
                }
                {
                    u64 u1 = f2mul(dt2, A2[1]);
                    u64 r1 = f2fma(u1, K24, K6);
                    r1 = f2fma(u1, r1, K05); r1 = f2fma(u1, r1, K1); r1 = f2fma(u1, r1, K1);
                    h[1] = f2fma(r1, h[1], f2mul(dtx2, Bv1));
                    yp = f2fma(h[1], Cv1, yp);
                }
                {
                    u64 u2 = f2mul(dt2, A2[2]);
                    u64 r2 = f2fma(u2, K24, K6);
                    r2 = f2fma(u2, r2, K05); r2 = f2fma(u2, r2, K1); r2 = f2fma(u2, r2, K1);
                    h[2] = f2fma(r2, h[2], f2mul(dtx2, Bv2));
                    yp = f2fma(h[2], Cv2, yp);
                }
                {
                    u64 u3 = f2mul(dt2, A2[3]);
                    u64 r3 = f2fma(u3, K24, K6);
                    r3 = f2fma(u3, r3, K05); r3 = f2fma(u3, r3, K1); r3 = f2fma(u3, r3, K1);
                    h[3] = f2fma(r3, h[3], f2mul(dtx2, Bv3));
                    yp = f2fma(h[3], Cv3, yp);
                }
                float y0, y1;
                unpk2(y0, y1, yp);
                float y = y0 + y1;
                y += __shfl_xor_sync(0xFFFFFFFFu, y, 4);
                y += __shfl_xor_sync(0xFFFFFFFFu, y, 2);
                y += __shfl_xor_sync(0xFFFFFFFFu, y, 1);
                if (sub == ti) yreg[r] = y * szv;
            }
        }
#pragma unroll
        for (int r = 0; r < 4; r++) {
            xbuf[r] = xn[r]; dbuf[r] = dn[r]; sbuf[r] = sn[r];
            yw[((size_t)b * T_DIM + c * SCAN_CHUNK + r * 8 + sub) * E_DIM + e] =
                __float2half(yreg[r]);
        }
    }
}

// ---------------------------------------------------------------------------
extern "C" void kernel_launch(void* const* d_in, const int* in_sizes, int n_in,
                              void* d_out, int out_size)
{
    (void)in_sizes; (void)n_in; (void)out_size;
    const float* x      = (const float*)d_in[0];
    const float* W_in   = (const float*)d_in[1];
    const float* W_conv = (const float*)d_in[2];
    const float* W_dt   = (const float*)d_in[3];
    const float* b_dt   = (const float*)d_in[4];
    const float* W_B    = (const float*)d_in[5];
    const float* W_C    = (const float*)d_in[6];
    const float* A_log  = (const float*)d_in[7];
    const float* W_out  = (const float*)d_in[8];
    float* out = (float*)d_out;

    float *xz, *xc, *dtb, *Bpp, *Cpp;
    __half *szh, *xh, *xch, *ywh;
    __half *WinTh, *WinTl, *WdtTh, *WoutTh, *WoutTl, *WbcH, *WbcL;
    cudaGetSymbolAddress((void**)&xz,  g_xz);
    cudaGetSymbolAddress((void**)&szh, g_szh);
    cudaGetSymbolAddress((void**)&xc,  g_xc);
    cudaGetSymbolAddress((void**)&dtb, g_dt);
    cudaGetSymbolAddress((void**)&Bpp, g_Bp);
    cudaGetSymbolAddress((void**)&Cpp, g_Cp);
    cudaGetSymbolAddress((void**)&xh,  g_xh);
    cudaGetSymbolAddress((void**)&xch, g_xch);
    cudaGetSymbolAddress((void**)&ywh, g_ywh);
    cudaGetSymbolAddress((void**)&WinTh,  g_WinTh);
    cudaGetSymbolAddress((void**)&WinTl,  g_WinTl);
    cudaGetSymbolAddress((void**)&WdtTh,  g_WdtTh);
    cudaGetSymbolAddress((void**)&WoutTh, g_WoutTh);
    cudaGetSymbolAddress((void**)&WoutTl, g_WoutTl);
    cudaGetSymbolAddress((void**)&WbcH,   g_WbcH);
    cudaGetSymbolAddress((void**)&WbcL,   g_WbcL);

    cudaFuncSetAttribute((const void*)gemm_mma<0, true>,  cudaFuncAttributeMaxDynamicSharedMemorySize, GEMM_SMEM);
    cudaFuncSetAttribute((const void*)gemm_mma<1, true>,  cudaFuncAttributeMaxDynamicSharedMemorySize, GEMM_SMEM);
    cudaFuncSetAttribute((const void*)gemm_mma<2, false>, cudaFuncAttributeMaxDynamicSharedMemorySize, GEMM_SMEM);
    cudaFuncSetAttribute((const void*)gemm_mma<3, true>,  cudaFuncAttributeMaxDynamicSharedMemorySize, GEMM_SMEM);
    cudaFuncSetAttribute((const void*)scan_kernel,        cudaFuncAttributeMaxDynamicSharedMemorySize, SCAN_SMEM);

    // 0) x -> fp16
    xcvt_kernel<<<(BT_DIM * D_DIM) / 512, 512>>>(x, xh);
    // 1) W_in transpose+split
    tsplit_kernel<<<dim3(4096 / 32, 1024 / 32), 256>>>(W_in, WinTh, WinTl, 1024, 4096);
    // 2) W_dt transpose (hi only)
    tsplit_kernel<<<dim3(2048 / 32, 2048 / 32), 256>>>(W_dt, WdtTh, nullptr, 2048, 2048);
    // 3) in-projection: x-half split fp32, z-half silu fp16  <-- ncu target
    gemm_mma<1, true><<<dim3(4096 / 128, BT_DIM / 128), 256, GEMM_SMEM>>>(
        xh, WinTh, WinTl, xz, nullptr, szh, nullptr, BT_DIM, 4096, 1024);
    // 4) conv along e + silu (+ fp16 copy)
    conv_silu_kernel<<<BT_DIM, 256>>>(xz, W_conv, xc, xch);
    // 5) dt projection (single-term) + softplus + clip
    gemm_mma<2, false><<<dim3(E_DIM / 128, BT_DIM / 128), 256, GEMM_SMEM>>>(
        xch, WdtTh, nullptr, dtb, nullptr, nullptr, b_dt, BT_DIM, E_DIM, E_DIM);
    // 6-7) W_B / W_C splits
    tsplit_kernel<<<dim3(64 / 32, 2048 / 32), 256>>>(W_B, WbcH,             WbcL,             2048, 64);
    tsplit_kernel<<<dim3(64 / 32, 2048 / 32), 256>>>(W_C, WbcH + 64 * 2048, WbcL + 64 * 2048, 2048, 64);
    // 8) B/C projections (split, one 128-wide block column)
    gemm_mma<3, true><<<dim3(1, BT_DIM / 128), 256, GEMM_SMEM>>>(
        xch, WbcH, WbcL, Bpp, Cpp, nullptr, nullptr, BT_DIM, 128, 2048);
    // 9) W_out split
    tsplit_kernel<<<dim3(1024 / 32, 2048 / 32), 256>>>(W_out, WoutTh, WoutTl, 2048, 1024);
    // 10) selective scan (fuses y * silu(z), emits fp16)
    scan_kernel<<<B_DIM * (E_DIM / 64), 512, SCAN_SMEM>>>(xc, dtb, Bpp, Cpp, szh, A_log, ywh);
    // 11) out projection (split) -> d_out
    gemm_mma<0, true><<<dim3(D_DIM / 128, BT_DIM / 128), 256, GEMM_SMEM>>>(
        ywh, WoutTh, WoutTl, out, nullptr, nullptr, nullptr, BT_DIM, D_DIM, E_DIM);
}

// round 17
// speedup vs baseline: 1.1337x; 1.0617x over previous
#include <cuda_runtime.h>
#include <cuda_fp16.h>
#include <cstdint>

#define E_DIM 2048
#define T_DIM 2048
#define B_DIM 4
#define D_DIM 1024
#define BT_DIM 8192
#define N_ST 64

typedef unsigned long long u64;

// ---------------- scratch (device globals; no allocation allowed) ----------
static __device__ __align__(1024) float  g_xz [(size_t)BT_DIM * E_DIM];
static __device__ __align__(1024) __half g_szh[(size_t)BT_DIM * E_DIM];
static __device__ __align__(1024) float  g_xc [(size_t)BT_DIM * E_DIM];
static __device__ __align__(1024) float  g_dt [(size_t)BT_DIM * E_DIM];
static __device__ __align__(1024) float  g_Bp [(size_t)BT_DIM * N_ST];
static __device__ __align__(1024) float  g_Cp [(size_t)BT_DIM * N_ST];
// fp16 activations
static __device__ __align__(1024) __half g_xh  [(size_t)BT_DIM * D_DIM];
static __device__ __align__(1024) __half g_xch [(size_t)BT_DIM * E_DIM];
static __device__ __align__(1024) __half g_ywh [(size_t)BT_DIM * E_DIM];
// fp16 hi/lo transposed weights [N,K]
static __device__ __align__(1024) __half g_WinTh [(size_t)4096 * 1024];
static __device__ __align__(1024) __half g_WinTl [(size_t)4096 * 1024];
static __device__ __align__(1024) __half g_WdtTh [(size_t)2048 * 2048];
static __device__ __align__(1024) __half g_WoutTh[(size_t)1024 * 2048];
static __device__ __align__(1024) __half g_WbcH  [(size_t)128 * 2048];
static __device__ __align__(1024) __half g_WbcL  [(size_t)128 * 2048];

__device__ __forceinline__ float silu_f(float v) { return v / (1.f + __expf(-v)); }

// ---------------- PTX helpers ----------------------------------------------
__device__ __forceinline__ uint32_t s2u(const void* p) {
    uint32_t a;
    asm("{ .reg .u64 t; cvta.to.shared.u64 t, %1; cvt.u32.u64 %0, t; }" : "=r"(a) : "l"(p));
    return a;
}
__device__ __forceinline__ uint32_t sw128(uint32_t off) { return off ^ ((off >> 3) & 0x70); }

#define CPA16(dst, src) asm volatile("cp.async.cg.shared.global [%0], [%1], 16;" :: "r"(dst), "l"(src))
#define CPA_COMMIT()    asm volatile("cp.async.commit_group;" ::: "memory")
#define CPA_WAIT2()     asm volatile("cp.async.wait_group 2;" ::: "memory")
#define CPA_WAIT1()     asm volatile("cp.async.wait_group 1;" ::: "memory")
#define CPA_WAIT0()     asm volatile("cp.async.wait_group 0;" ::: "memory")

__device__ __forceinline__ void ldsm4(uint32_t r[4], uint32_t a) {
    asm volatile("ldmatrix.sync.aligned.m8n8.x4.shared.b16 {%0,%1,%2,%3}, [%4];"
        : "=r"(r[0]), "=r"(r[1]), "=r"(r[2]), "=r"(r[3]) : "r"(a));
}
__device__ __forceinline__ void mma_f16(float c[4], const uint32_t a[4],
                                        uint32_t b0, uint32_t b1) {
    asm volatile(
        "mma.sync.aligned.m16n8k16.row.col.f32.f16.f16.f32 "
        "{%0,%1,%2,%3}, {%4,%5,%6,%7}, {%8,%9}, {%0,%1,%2,%3};"
        : "+f"(c[0]), "+f"(c[1]), "+f"(c[2]), "+f"(c[3])
        : "r"(a[0]), "r"(a[1]), "r"(a[2]), "r"(a[3]), "r"(b0), "r"(b1));
}

// packed f32x2
__device__ __forceinline__ u64 pk2(float x, float y) {
    u64 r; asm("mov.b64 %0,{%1,%2};" : "=l"(r) : "f"(x), "f"(y)); return r;
}
__device__ __forceinline__ void unpk2(float& x, float& y, u64 v) {
    asm("mov.b64 {%0,%1}, %2;" : "=f"(x), "=f"(y) : "l"(v));
}
__device__ __forceinline__ u64 f2fma(u64 a, u64 b, u64 c) {
    u64 d; asm("fma.rn.f32x2 %0,%1,%2,%3;" : "=l"(d) : "l"(a), "l"(b), "l"(c)); return d;
}
__device__ __forceinline__ u64 f2mul(u64 a, u64 b) {
    u64 d; asm("mul.rn.f32x2 %0,%1,%2;" : "=l"(d) : "l"(a), "l"(b)); return d;
}
__device__ __forceinline__ void lds2x64(u64& a, u64& b, uint32_t addr) {
    asm volatile("ld.shared.v2.b64 {%0,%1}, [%2];" : "=l"(a), "=l"(b) : "r"(addr));
}

// ---------------- HMMA fp16 GEMM: C[M,N] = A[M,K] * W[K,N] -----------------
// CTA 128x128, BK=64, 8 warps (2m x 4n), warp tile 64x32, 2-stage cp.async.
// MODE 0: plain fp32 store, stride N
// MODE 1: logical N=4096; n0<2048 -> C0 raw fp32 (split); n0>=2048 ->
//         Hz = __half(silu(v)) stride 2048 (no split)
// MODE 2: softplus(v + bias[col]) clipped [1e-3,1e-1], stride N
// MODE 3: logical N=128 in ONE block col; col<64 -> C0, else C1, stride 64
#define G2_STAGE 49152
#define GEMM_SMEM (2 * G2_STAGE)

template <int MODE, bool SPLIT>
__global__ __launch_bounds__(256, 2)
void gemm_mma(const __half* __restrict__ Ax, const __half* __restrict__ Bh,
              const __half* __restrict__ Bl,
              float* __restrict__ C0, float* __restrict__ C1,
              __half* __restrict__ Hz,
              const float* __restrict__ bias, int M, int N, int K)
{
    extern __shared__ __align__(1024) char smem[];
    const uint32_t su = s2u(smem);
    const int tid = threadIdx.x;
    const int wid = tid >> 5, lane = tid & 31;
    const int wm = wid & 1, wn = wid >> 1;
    const int n0 = blockIdx.x * 128;
    const int m0 = blockIdx.y * 128;
    const int NT = K >> 6;
    const bool lo_on = SPLIT && (MODE != 1 || n0 < 2048);

    const __half* srcA  = Ax + (size_t)m0 * K;
    const __half* srcBh = Bh + (size_t)n0 * K;
    const __half* srcBl = Bl ? (Bl + (size_t)n0 * K) : nullptr;

    auto load_stage = [&](int st, int kc) {
        const uint32_t sbase = su + st * G2_STAGE;
        {
            const __half* g0 = srcA + kc * 64;
#pragma unroll
            for (int i = 0; i < 4; i++) {
                int c = tid + i * 256;
                int row = c >> 3, ch = c & 7;
                CPA16(sbase + sw128(row * 128 + ch * 16),
                      g0 + (size_t)row * K + ch * 8);
            }
        }
        {
            const __half* g0 = srcBh + kc * 64;
#pragma unroll
            for (int i = 0; i < 4; i++) {
                int c = tid + i * 256;
                int row = c >> 3, ch = c & 7;
                CPA16(sbase + 16384 + sw128(row * 128 + ch * 16),
                      g0 + (size_t)row * K + ch * 8);
            }
        }
        if (lo_on) {
            const __half* g0 = srcBl + kc * 64;
#pragma unroll
            for (int i = 0; i < 4; i++) {
                int c = tid + i * 256;
                int row = c >> 3, ch = c & 7;
                CPA16(sbase + 32768 + sw128(row * 128 + ch * 16),
                      g0 + (size_t)row * K + ch * 8);
            }
        }
        CPA_COMMIT();
    };

    float acc[4][4][4];
#pragma unroll
    for (int a = 0; a < 4; a++)
#pragma unroll
        for (int b = 0; b < 4; b++)
#pragma unroll
            for (int c = 0; c < 4; c++) acc[a][b][c] = 0.f;

    load_stage(0, 0);

    const int arow = lane & 15;
    const int khalf = lane >> 4;

    uint32_t aAddr[4], bhAddr[2], blAddr[2];
#pragma unroll
    for (int mt = 0; mt < 4; mt++) {
        int r = wm * 64 + mt * 16 + arow;
        aAddr[mt] = su + sw128(r * 128 + khalf * 16);
    }
#pragma unroll
    for (int bt = 0; bt < 2; bt++) {
        int r = wn * 32 + bt * 16 + arow;
        uint32_t sw = sw128(r * 128 + khalf * 16);
        bhAddr[bt] = su + 16384 + sw;
        blAddr[bt] = su + 32768 + sw;
    }

    for (int t = 0; t < NT; ++t) {
        if (t + 1 < NT) { load_stage((t + 1) & 1, t + 1); CPA_WAIT1(); }
        else             CPA_WAIT0();
        __syncthreads();

        const uint32_t soff = (t & 1) * G2_STAGE;
#pragma unroll
        for (int kk = 0; kk < 4; kk++) {
            const uint32_t kx = kk * 32;
            uint32_t bHf[2][4], bLf[2][4];
#pragma unroll
            for (int bt = 0; bt < 2; bt++)
                ldsm4(bHf[bt], (bhAddr[bt] + soff) ^ kx);
            if (lo_on) {
#pragma unroll
                for (int bt = 0; bt < 2; bt++)
                    ldsm4(bLf[bt], (blAddr[bt] + soff) ^ kx);
            }
#pragma unroll
            for (int mt = 0; mt < 4; mt++) {
                uint32_t aF[4];
                ldsm4(aF, (aAddr[mt] + soff) ^ kx);
#pragma unroll
                for (int bt = 0; bt < 2; bt++)
#pragma unroll
                    for (int o = 0; o < 2; o++) {
                        const int j = bt * 2 + o;
                        mma_f16(acc[mt][j], aF, bHf[bt][o], bHf[bt][o + 2]);
                        if (lo_on)
                            mma_f16(acc[mt][j], aF, bLf[bt][o], bLf[bt][o + 2]);
                    }
            }
        }
        __syncthreads();
    }

    // ---------------- epilogue ----------------------------------------------
    const int rbase = m0 + wm * 64 + (lane >> 2);
    const int cbase = n0 + wn * 32 + (lane & 3) * 2;
#pragma unroll
    for (int mt = 0; mt < 4; mt++) {
#pragma unroll
        for (int j = 0; j < 4; j++) {
            const int col = cbase + j * 8;
#pragma unroll
            for (int half = 0; half < 2; half++) {
                const int m = rbase + mt * 16 + half * 8;
                float v0 = acc[mt][j][half * 2];
                float v1 = acc[mt][j][half * 2 + 1];
                if (MODE == 0) {
                    *(float2*)(C0 + (size_t)m * N + col) = make_float2(v0, v1);
                } else if (MODE == 1) {
                    if (n0 < 2048)
                        *(float2*)(C0 + (size_t)m * 2048 + col) = make_float2(v0, v1);
                    else {
                        __half2 hv;
                        hv.x = __float2half(silu_f(v0));
                        hv.y = __float2half(silu_f(v1));
                        *(__half2*)(Hz + (size_t)m * 2048 + (col - 2048)) = hv;
                    }
                } else if (MODE == 2) {
                    float u0 = v0 + bias[col], u1 = v1 + bias[col + 1];
                    float s0 = (u0 > 15.f) ? u0 : log1pf(__expf(u0));
                    float s1 = (u1 > 15.f) ? u1 : log1pf(__expf(u1));
                    s0 = fminf(fmaxf(s0, 0.001f), 0.1f);
                    s1 = fminf(fmaxf(s1, 0.001f), 0.1f);
                    *(float2*)(C0 + (size_t)m * N + col) = make_float2(s0, s1);
                } else {
                    if (col < 64)
                        *(float2*)(C0 + (size_t)m * 64 + col) = make_float2(v0, v1);
                    else
                        *(float2*)(C1 + (size_t)m * 64 + (col - 64)) = make_float2(v0, v1);
                }
            }
        }
    }
}

// ---------------- weight transpose + fp16 hi/lo split -----------------------
__global__ __launch_bounds__(256)
void tsplit_kernel(const float* __restrict__ in, __half* __restrict__ oh,
                   __half* __restrict__ ol, int K, int N)
{
    __shared__ float tile[32][33];
    const int n0 = blockIdx.x * 32, k0 = blockIdx.y * 32;
    const int tx = threadIdx.x & 31, ty = threadIdx.x >> 5;
#pragma unroll
    for (int i = 0; i < 4; i++)
        tile[ty + i * 8][tx] = in[(size_t)(k0 + ty + i * 8) * N + n0 + tx];
    __syncthreads();
#pragma unroll
    for (int i = 0; i < 4; i++) {
        float v = tile[tx][ty + i * 8];
        __half h = __float2half(v);
        size_t o = (size_t)(n0 + ty + i * 8) * K + k0 + tx;
        oh[o] = h;
        if (ol) ol[o] = __float2half(v - __half2float(h));
    }
}

// ---------------- x -> fp16 --------------------------------------------------
__global__ __launch_bounds__(512)
void xcvt_kernel(const float* __restrict__ x, __half* __restrict__ oh)
{
    size_t i = (size_t)blockIdx.x * 512 + threadIdx.x;
    oh[i] = __float2half(x[i]);
}

// ---------------- conv along e, weights indexed by t, + silu ----------------
__global__ __launch_bounds__(256)
void conv_silu_kernel(const float* __restrict__ xz, const float* __restrict__ Wc,
                      float* __restrict__ xc, __half* __restrict__ xch)
{
    __shared__ float s[E_DIM + 4];
    const int row = blockIdx.x;
    const int t = row & (T_DIM - 1);
    const int tid = threadIdx.x;
    const float* src = xz + (size_t)row * E_DIM;
#pragma unroll
    for (int j = 0; j < E_DIM / 256; ++j)
        s[tid + j * 256 + 1] = src[tid + j * 256];
    if (tid == 0) s[0] = 0.f;
    if (tid < 3) s[E_DIM + 1 + tid] = 0.f;
    __syncthreads();
    const float w0 = Wc[t], w1 = Wc[E_DIM + t], w2 = Wc[2 * E_DIM + t], w3 = Wc[3 * E_DIM + t];
    const size_t base = (size_t)row * E_DIM;
#pragma unroll
    for (int j = 0; j < E_DIM / 256; ++j) {
        int e = tid + j * 256;
        float v = w0 * s[e] + w1 * s[e + 1] + w2 * s[e + 2] + w3 * s[e + 3];
        float sv = silu_f(v);
        xc[base + e] = sv;
        xch[base + e] = __float2half(sv);
    }
}

// ---------------- selective scan v3 (sz fp16) --------------------------------
#define SCAN_CHUNK 32
#define SCAN_NCH   (T_DIM / SCAN_CHUNK)
#define SCAN_SMEM  (4 * 2 * SCAN_CHUNK * N_ST * 4)   // 65536

__global__ __launch_bounds__(512)
void scan_kernel(const float* __restrict__ xc, const float* __restrict__ dt,
                 const float* __restrict__ Bp, const float* __restrict__ Cp,
                 const __half* __restrict__ szh, const float* __restrict__ A_log,
                 __half* __restrict__ yw)
{
    extern __shared__ __align__(1024) char ssm[];
    const uint32_t sbase = s2u(ssm);
    const int tid  = threadIdx.x;
    const int warp = tid >> 5, lane = tid & 31;
    const int sub  = lane & 7;
    const int e0 = (blockIdx.x & 31) * 64;
    const int b  = blockIdx.x >> 5;
    const int e  = e0 + warp * 4 + (lane >> 3);
    const size_t base = ((size_t)b * T_DIM) * E_DIM + e;
    const float* BpB = Bp + (size_t)b * T_DIM * N_ST;
    const float* CpB = Cp + (size_t)b * T_DIM * N_ST;

    u64 A2[4];
#pragma unroll
    for (int p = 0; p < 4; p++)
        A2[p] = pk2(-__expf(A_log[sub * 8 + 2 * p]),
                    -__expf(A_log[sub * 8 + 2 * p + 1]));
    const u64 K24 = pk2(1.f / 24.f, 1.f / 24.f);
    const u64 K6  = pk2(1.f / 6.f, 1.f / 6.f);
    const u64 K05 = pk2(0.5f, 0.5f);
    const u64 K1  = pk2(1.f, 1.f);

    auto issue_chunk = [&](int c) {
        if (c < SCAN_NCH) {
            const uint32_t bufo = sbase + (c & 3) * 16384;
            const float* gB = BpB + (size_t)c * SCAN_CHUNK * N_ST;
            const float* gC = CpB + (size_t)c * SCAN_CHUNK * N_ST;
            CPA16(bufo + tid * 16,        gB + tid * 4);
            CPA16(bufo + 8192 + tid * 16, gC + tid * 4);
        }
        CPA_COMMIT();
    };

    issue_chunk(0); issue_chunk(1); issue_chunk(2);

    float xbuf[4], dbuf[4], sbuf[4];
#pragma unroll
    for (int r = 0; r < 4; r++) {
        const size_t off = base + (size_t)(r * 8 + sub) * E_DIM;
        xbuf[r] = xc[off]; dbuf[r] = dt[off]; sbuf[r] = __half2float(szh[off]);
    }

    u64 h[4] = {0, 0, 0, 0};
    float yreg[4];

    for (int c = 0; c < SCAN_NCH; ++c) {
        CPA_WAIT2();
        __syncthreads();
        issue_chunk(c + 3);

        float xn[4], dn[4], sn[4];
        if (c + 1 < SCAN_NCH) {
#pragma unroll
            for (int r = 0; r < 4; r++) {
                const size_t off = base + (size_t)((c + 1) * SCAN_CHUNK + r * 8 + sub) * E_DIM;
                xn[r] = xc[off]; dn[r] = dt[off]; sn[r] = __half2float(szh[off]);
            }
        } else {
#pragma unroll
            for (int r = 0; r < 4; r++) { xn[r] = 0.f; dn[r] = 0.f; sn[r] = 0.f; }
        }

        const uint32_t bufo = sbase + (c & 3) * 16384 + sub * 32;
#pragma unroll
        for (int r = 0; r < 4; r++) {
#pragma unroll
            for (int ti = 0; ti < 8; ti++) {
                const int tt = r * 8 + ti;
                const float xv  = __shfl_sync(0xFFFFFFFFu, xbuf[r], ti, 8);
                const float dtv = __shfl_sync(0xFFFFFFFFu, dbuf[r], ti, 8);
                const float szv = __shfl_sync(0xFFFFFFFFu, sbuf[r], ti, 8);
                u64 Bv0, Bv1, Bv2, Bv3, Cv0, Cv1, Cv2, Cv3;
                lds2x64(Bv0, Bv1, bufo + tt * 256);
                lds2x64(Bv2, Bv3, bufo + tt * 256 + 16);
                lds2x64(Cv0, Cv1, bufo + 8192 + tt * 256);
                lds2x64(Cv2, Cv3, bufo + 8192 + tt * 256 + 16);

                const u64 dt2  = pk2(dtv, dtv);
                const float dtx = dtv * xv;
                const u64 dtx2 = pk2(dtx, dtx);

                u64 yp;
                {
                    u64 u0 = f2mul(dt2, A2[0]);
                    u64 r0 = f2fma(u0, K24, K6);
                    r0 = f2fma(u0, r0, K05); r0 = f2fma(u0, r0, K1); r0 = f2fma(u0, r0, K1);
                    h[0] = f2fma(r0, h[0], f2mul(dtx2, Bv0));
                    yp = f2mul(h[0], Cv0);
                }
                {
                    u64 u1 = f2mul(dt2, A2[1]);
                    u64 r1 = f2fma(u1, K24, K6);
                    r1 = f2fma(u1, r1, K05); r1 = f2fma(u1, r1, K1); r1 = f2fma(u1, r1, K1);
                    h[1] = f2fma(r1, h[1], f2mul(dtx2, Bv1));
                    yp = f2fma(h[1], Cv1, yp);
                }
                {
                    u64 u2 = f2mul(dt2, A2[2]);
                    u64 r2 = f2fma(u2, K24, K6);
                    r2 = f2fma(u2, r2, K05); r2 = f2fma(u2, r2, K1); r2 = f2fma(u2, r2, K1);
                    h[2] = f2fma(r2, h[2], f2mul(dtx2, Bv2));
                    yp = f2fma(h[2], Cv2, yp);
                }
                {
                    u64 u3 = f2mul(dt2, A2[3]);
                    u64 r3 = f2fma(u3, K24, K6);
                    r3 = f2fma(u3, r3, K05); r3 = f2fma(u3, r3, K1); r3 = f2fma(u3, r3, K1);
                    h[3] = f2fma(r3, h[3], f2mul(dtx2, Bv3));
                    yp = f2fma(h[3], Cv3, yp);
                }
                float y0, y1;
                unpk2(y0, y1, yp);
                float y = y0 + y1;
                y += __shfl_xor_sync(0xFFFFFFFFu, y, 4);
                y += __shfl_xor_sync(0xFFFFFFFFu, y, 2);
                y += __shfl_xor_sync(0xFFFFFFFFu, y, 1);
                if (sub == ti) yreg[r] = y * szv;
            }
        }
#pragma unroll
        for (int r = 0; r < 4; r++) {
            xbuf[r] = xn[r]; dbuf[r] = dn[r]; sbuf[r] = sn[r];
            yw[((size_t)b * T_DIM + c * SCAN_CHUNK + r * 8 + sub) * E_DIM + e] =
                __float2half(yreg[r]);
        }
    }
}

// ---------------------------------------------------------------------------
extern "C" void kernel_launch(void* const* d_in, const int* in_sizes, int n_in,
                              void* d_out, int out_size)
{
    (void)in_sizes; (void)n_in; (void)out_size;
    const float* x      = (const float*)d_in[0];
    const float* W_in   = (const float*)d_in[1];
    const float* W_conv = (const float*)d_in[2];
    const float* W_dt   = (const float*)d_in[3];
    const float* b_dt   = (const float*)d_in[4];
    const float* W_B    = (const float*)d_in[5];
    const float* W_C    = (const float*)d_in[6];
    const float* A_log  = (const float*)d_in[7];
    const float* W_out  = (const float*)d_in[8];
    float* out = (float*)d_out;

    float *xz, *xc, *dtb, *Bpp, *Cpp;
    __half *szh, *xh, *xch, *ywh;
    __half *WinTh, *WinTl, *WdtTh, *WoutTh, *WbcH, *WbcL;
    cudaGetSymbolAddress((void**)&xz,  g_xz);
    cudaGetSymbolAddress((void**)&szh, g_szh);
    cudaGetSymbolAddress((void**)&xc,  g_xc);
    cudaGetSymbolAddress((void**)&dtb, g_dt);
    cudaGetSymbolAddress((void**)&Bpp, g_Bp);
    cudaGetSymbolAddress((void**)&Cpp, g_Cp);
    cudaGetSymbolAddress((void**)&xh,  g_xh);
    cudaGetSymbolAddress((void**)&xch, g_xch);
    cudaGetSymbolAddress((void**)&ywh, g_ywh);
    cudaGetSymbolAddress((void**)&WinTh,  g_WinTh);
    cudaGetSymbolAddress((void**)&WinTl,  g_WinTl);
    cudaGetSymbolAddress((void**)&WdtTh,  g_WdtTh);
    cudaGetSymbolAddress((void**)&WoutTh, g_WoutTh);
    cudaGetSymbolAddress((void**)&WbcH,   g_WbcH);
    cudaGetSymbolAddress((void**)&WbcL,   g_WbcL);

    cudaFuncSetAttribute((const void*)gemm_mma<0, false>, cudaFuncAttributeMaxDynamicSharedMemorySize, GEMM_SMEM);
    cudaFuncSetAttribute((const void*)gemm_mma<1, true>,  cudaFuncAttributeMaxDynamicSharedMemorySize, GEMM_SMEM);
    cudaFuncSetAttribute((const void*)gemm_mma<2, false>, cudaFuncAttributeMaxDynamicSharedMemorySize, GEMM_SMEM);
    cudaFuncSetAttribute((const void*)gemm_mma<3, true>,  cudaFuncAttributeMaxDynamicSharedMemorySize, GEMM_SMEM);
    cudaFuncSetAttribute((const void*)scan_kernel,        cudaFuncAttributeMaxDynamicSharedMemorySize, SCAN_SMEM);

    // 0) x -> fp16
    xcvt_kernel<<<(BT_DIM * D_DIM) / 512, 512>>>(x, xh);
    // 1) W_in transpose+split
    tsplit_kernel<<<dim3(4096 / 32, 1024 / 32), 256>>>(W_in, WinTh, WinTl, 1024, 4096);
    // 2) W_dt transpose (hi only)
    tsplit_kernel<<<dim3(2048 / 32, 2048 / 32), 256>>>(W_dt, WdtTh, nullptr, 2048, 2048);
    // 3) in-projection: x-half split fp32, z-half silu fp16  <-- ncu target
    gemm_mma<1, true><<<dim3(4096 / 128, BT_DIM / 128), 256, GEMM_SMEM>>>(
        xh, WinTh, WinTl, xz, nullptr, szh, nullptr, BT_DIM, 4096, 1024);
    // 4) conv along e + silu (+ fp16 copy)
    conv_silu_kernel<<<BT_DIM, 256>>>(xz, W_conv, xc, xch);
    // 5) dt projection (single-term) + softplus + clip
    gemm_mma<2, false><<<dim3(E_DIM / 128, BT_DIM / 128), 256, GEMM_SMEM>>>(
        xch, WdtTh, nullptr, dtb, nullptr, nullptr, b_dt, BT_DIM, E_DIM, E_DIM);
    // 6-7) W_B / W_C splits
    tsplit_kernel<<<dim3(64 / 32, 2048 / 32), 256>>>(W_B, WbcH,             WbcL,             2048, 64);
    tsplit_kernel<<<dim3(64 / 32, 2048 / 32), 256>>>(W_C, WbcH + 64 * 2048, WbcL + 64 * 2048, 2048, 64);
    // 8) B/C projections (split, one 128-wide block column)
    gemm_mma<3, true><<<dim3(1, BT_DIM / 128), 256, GEMM_SMEM>>>(
        xch, WbcH, WbcL, Bpp, Cpp, nullptr, nullptr, BT_DIM, 128, 2048);
    // 9) W_out transpose (hi only)
    tsplit_kernel<<<dim3(1024 / 32, 2048 / 32), 256>>>(W_out, WoutTh, nullptr, 2048, 1024);
    // 10) selective scan (fuses y * silu(z), emits fp16)
    scan_kernel<<<B_DIM * (E_DIM / 64), 512, SCAN_SMEM>>>(xc, dtb, Bpp, Cpp, szh, A_log, ywh);
    // 11) out projection (single-term) -> d_out
    gemm_mma<0, false><<<dim3(D_DIM / 128, BT_DIM / 128), 256, GEMM_SMEM>>>(
        ywh, WoutTh, nullptr, out, nullptr, nullptr, nullptr, BT_DIM, D_DIM, E_DIM);
}